// round 16
// baseline (speedup 1.0000x reference)
#include <cuda_runtime.h>
#include <cuda_bf16.h>
#include <cstdint>

#define BB 8
#define CC 64
#define OO 64
#define HH 96
#define WW 96
#define HW (HH*WW)
#define K2 9
#define NOFF 18
#define WP 100              // padded width/height
#define XTB (WP*WP*CC)

typedef unsigned long long ull;
typedef unsigned short ushort_t;

#define SW128(off) ((off) ^ (((off) >> 3) & 0x70))

__device__ __forceinline__ uint32_t smem_u32(const void* p) {
    uint32_t a;
    asm("{ .reg .u64 t; cvta.to.shared.u64 t, %1; cvt.u32.u64 %0, t; }" : "=r"(a) : "l"(p));
    return a;
}

#define LDSM_X4(r0, r1, r2, r3, addr) \
    asm volatile("ldmatrix.sync.aligned.m8n8.x4.shared.b16 {%0,%1,%2,%3}, [%4];" \
                 : "=r"(r0), "=r"(r1), "=r"(r2), "=r"(r3) : "r"(addr))

#define MMA16816(ac, a0, a1, a2, a3, b0, b1) \
    asm volatile("mma.sync.aligned.m16n8k16.row.col.f32.bf16.bf16.f32 " \
                 "{%0,%1,%2,%3}, {%4,%5,%6,%7}, {%8,%9}, {%0,%1,%2,%3};" \
                 : "+f"((ac)[0]), "+f"((ac)[1]), "+f"((ac)[2]), "+f"((ac)[3]) \
                 : "r"(a0), "r"(a1), "r"(a2), "r"(a3), "r"(b0), "r"(b1))

#define CP_ASYNC16(dst, src) \
    asm volatile("cp.async.cg.shared.global [%0], [%1], 16;" :: "r"(dst), "l"(src))
#define CP_COMMIT() asm volatile("cp.async.commit_group;")
#define CP_WAIT0()  asm volatile("cp.async.wait_group 0;")

#define BF16_SPLIT(sx, sy, hp, lp) do { \
    asm("cvt.rn.bf16x2.f32 %0, %1, %2;" : "=r"(hp) : "f"(sy), "f"(sx)); \
    float _hx = __uint_as_float((hp) << 16); \
    float _hy = __uint_as_float((hp) & 0xffff0000u); \
    asm("cvt.rn.bf16x2.f32 %0, %1, %2;" : "=r"(lp) : "f"((sy) - _hy), "f"((sx) - _hx)); \
} while (0)

// ---------------- scratch -----------------------------------------------------
__device__ float   g_xt[BB * XTB];             // padded NHWC x (zero border)
__device__ int     g_pidx[BB * K2 * HW];       // base idx (0 => zero corner if far)
__device__ float2  g_pw2[BB * K2 * HW];        // raw fractions (wy, wx)
__device__ ushort_t g_bst[K2 * 2 * 4096];      // conv_w bf16 [tap][hi/lo], SW128
__device__ ushort_t g_obst[K2 * 2 * 2048];     // offset_w bf16 [tap][hi/lo][32n][64c], SW128

// ---------------- transpose NCHW -> padded NHWC --------------------------------
__global__ void transpose_x_kernel(const float* __restrict__ x, float* __restrict__ xt) {
    __shared__ float tile[32][33];
    int blk = blockIdx.x;
    int pt = blk % 288, ct = (blk / 288) & 1, b = blk / 576;
    int lx = threadIdx.x & 31, ly = threadIdx.x >> 5;
    int p0 = pt * 32, c0 = ct * 32;
    int h = p0 / WW, w0 = p0 - h * WW;
    const float* xb = x + (size_t)(b * CC + c0) * HW + p0;
#pragma unroll
    for (int i = 0; i < 4; i++) {
        int cc = ly + 8 * i;
        tile[cc][lx] = xb[(size_t)cc * HW + lx];
    }
    __syncthreads();
    float* xo = xt + (size_t)b * XTB + ((size_t)(h + 2) * WP + (w0 + 2)) * CC + c0;
#pragma unroll
    for (int i = 0; i < 4; i++) {
        int pp = ly + 8 * i;
        xo[(size_t)pp * CC + lx] = tile[lx][pp];
    }
}

// ---------------- weight prep (both B matrices pre-swizzled) --------------------
__global__ void build_weights_kernel(const float* __restrict__ cw,
                                     const float* __restrict__ ow,
                                     ushort_t* __restrict__ bst,
                                     ushort_t* __restrict__ obst) {
    int idx = blockIdx.x * 256 + threadIdx.x;
    if (idx < K2 * OO * CC) {        // conv_w -> [tap][hi/lo][64o][64c]
        int k = idx / (OO * CC);
        int r = idx % (OO * CC);
        int o = r / CC;
        int c = r % CC;
        float v = cw[(size_t)(o * CC + c) * K2 + k];
        __nv_bfloat16 h = __float2bfloat16(v);
        __nv_bfloat16 l = __float2bfloat16(v - __bfloat162float(h));
        uint32_t sw = SW128((uint32_t)(o * 128 + c * 2)) >> 1;
        bst[(k * 2 + 0) * 4096 + sw] = *(ushort_t*)&h;
        bst[(k * 2 + 1) * 4096 + sw] = *(ushort_t*)&l;
    }
    if (idx < K2 * 32 * CC) {        // offset_w -> [tap][hi/lo][32n pad][64c]
        int k = idx / (32 * CC);
        int r = idx % (32 * CC);
        int n = r / CC;
        int c = r % CC;
        float v = (n < NOFF) ? ow[(size_t)(n * CC + c) * K2 + k] : 0.f;
        __nv_bfloat16 h = __float2bfloat16(v);
        __nv_bfloat16 l = __float2bfloat16(v - __bfloat162float(h));
        uint32_t sw = SW128((uint32_t)(n * 128 + c * 2)) >> 1;
        obst[(k * 2 + 0) * 2048 + sw] = *(ushort_t*)&h;
        obst[(k * 2 + 1) * 2048 + sw] = *(ushort_t*)&l;
    }
}

// ---------------- offset conv as HMMA (FULL 3-pass split) + position precompute -
// 256 thr, tile 64 px x 32 out, 4 CTAs/SM.
// smem: A 2buf x (hi 8192 + lo 8192) = 32768; B at 32768: 2buf x (hi 4096 + lo 4096)
#define OSM_B   32768
#define OSM_TOT 49152

__global__ void __launch_bounds__(256, 4)
offset_mma_kernel(const float* __restrict__ xt, const ushort_t* __restrict__ obst,
                  const float* __restrict__ ob,
                  int* __restrict__ pidx, float2* __restrict__ pw2)
{
    extern __shared__ char smc[];
    uint32_t sbase = smem_u32(smc);
    int tid = threadIdx.x, wid = tid >> 5, lane = tid & 31;
    int b  = blockIdx.x / 144;
    int p0 = (blockIdx.x % 144) * 64;

    const float* xt_b = xt + (size_t)b * XTB;
    int c2 = 2 * lane;
    int mt = wid & 3;      // m16 tile
    int ng = wid >> 2;     // n group: 2 n8-tiles

    float acc[2][4];
#pragma unroll
    for (int i = 0; i < 2; i++)
#pragma unroll
        for (int j = 0; j < 4; j++) acc[i][j] = 0.f;

    int lr = lane & 7;
    uint32_t la0 = (uint32_t)((mt * 16 + lr + ((lane >> 3) & 1) * 8) * 128 + (lane >> 4) * 16);
    uint32_t lb0 = (uint32_t)((ng * 16 + lr + (lane >> 4) * 8) * 128 + ((lane >> 3) & 1) * 16);

    auto stageB = [&](int k, int buf) {
        const char* src = (const char*)(obst) + (size_t)k * 8192;
        uint32_t dst = sbase + OSM_B + (uint32_t)buf * 8192;
        {
            int e = tid;           // 512 uint4 total
            CP_ASYNC16(dst + (uint32_t)e * 16, src + (size_t)e * 16);
            e = tid + 256;
            CP_ASYNC16(dst + (uint32_t)e * 16, src + (size_t)e * 16);
        }
        CP_COMMIT();
    };
    auto fill = [&](int k, int buf) {
        int dyk = k / 3, dxk = k % 3;
        char* Ab = smc + buf * 16384;
#pragma unroll
        for (int j = 0; j < 8; j++) {
            int px = wid + 8 * j;
            int p = p0 + px;
            int h = p / WW, w = p - h * WW;
            const float* base = xt_b + ((size_t)(h + dyk + 1) * WP + (w + dxk + 1)) * CC + c2;
            float2 g = *(const float2*)base;
            uint32_t hp, lp;
            BF16_SPLIT(g.x, g.y, hp, lp);
            uint32_t sw = SW128((uint32_t)(px * 128 + lane * 4));
            *(uint32_t*)(Ab + sw)        = hp;
            *(uint32_t*)(Ab + 8192 + sw) = lp;
        }
    };

    stageB(0, 0);
    fill(0, 0);
    CP_WAIT0();
    __syncthreads();

    for (int k = 0; k < 9; k++) {
        int buf = k & 1;
        if (k < 8) stageB(k + 1, buf ^ 1);

        uint32_t Abase = sbase + (uint32_t)buf * 16384;
        uint32_t Bbase = sbase + OSM_B + (uint32_t)buf * 8192;
#pragma unroll
        for (int ks = 0; ks < 4; ks++) {
            uint32_t la = SW128(la0 + ks * 32);
            uint32_t lb = SW128(lb0 + ks * 32);
            uint32_t ah0, ah1, ah2, ah3, al0, al1, al2, al3;
            LDSM_X4(ah0, ah1, ah2, ah3, Abase + la);
            LDSM_X4(al0, al1, al2, al3, Abase + la + 8192);
            uint32_t bh[4];
            LDSM_X4(bh[0], bh[1], bh[2], bh[3], Bbase + lb);
            MMA16816(acc[0], ah0, ah1, ah2, ah3, bh[0], bh[1]);
            MMA16816(acc[1], ah0, ah1, ah2, ah3, bh[2], bh[3]);
            MMA16816(acc[0], al0, al1, al2, al3, bh[0], bh[1]);
            MMA16816(acc[1], al0, al1, al2, al3, bh[2], bh[3]);
            uint32_t bl[4];
            LDSM_X4(bl[0], bl[1], bl[2], bl[3], Bbase + 4096 + lb);
            MMA16816(acc[0], ah0, ah1, ah2, ah3, bl[0], bl[1]);
            MMA16816(acc[1], ah0, ah1, ah2, ah3, bl[2], bl[3]);
        }

        if (k < 8) {
            fill(k + 1, buf ^ 1);
            CP_WAIT0();
        }
        __syncthreads();
    }

    // ---- epilogue: offsets -> positions, written straight to pidx/pw2 ----
    int px0 = p0 + mt * 16 + (lane >> 2);
#pragma unroll
    for (int nt = 0; nt < 2; nt++) {
        int n0 = ng * 16 + nt * 8 + 2 * (lane & 3);
        int t = n0 >> 1;
        if (t < 9) {
            float bdy = ob[n0], bdx = ob[n0 + 1];
            int tdy = t / 3 - 1, tdx = t % 3 - 1;
#pragma unroll
            for (int half = 0; half < 2; half++) {
                int p = px0 + 8 * half;
                float dy = acc[nt][2 * half]     + bdy;
                float dx = acc[nt][2 * half + 1] + bdx;
                int h = p / WW, w = p - h * WW;
                float py = (float)(h + tdy) + dy;
                float qx = (float)(w + tdx) + dx;
                float fy = floorf(py), fx = floorf(qx);
                int y0 = (int)fy, x0i = (int)fx;
                float wy = py - fy, wx = qx - fx;
                bool far = (y0 < -2) | (y0 > 96) | (x0i < -2) | (x0i > 96);
                int idx = far ? 0 : ((y0 + 2) * WP + (x0i + 2)) * CC;
                size_t gp = ((size_t)(b * 9 + t)) * HW + p;
                pidx[gp] = idx;
                pw2[gp]  = make_float2(wy, wx);
            }
        }
    }
}

// ---------------- fused: 128-px tile, m32n16 warp tile, 512 thr, 2 CTAs/SM ------
// smem: A 2buf x (hi 16384 + lo 16384) = 65536
//       B at 65536: 2buf x (hi 8192 + lo 8192) = 32768
//       sIdx at 98304 (1152 int), sFrac at 102912 (1152 float2)
#define SM_B    65536
#define SM_IDX  98304
#define SM_FR   102912
#define SM_TOT  112128

__global__ void __launch_bounds__(512, 2)
fused_mma_kernel(const float* __restrict__ xt, const int* __restrict__ pidx,
                 const float2* __restrict__ pw2, const ushort_t* __restrict__ bst,
                 const float* __restrict__ cb, float* __restrict__ out)
{
    extern __shared__ char smc[];
    uint32_t sbase = smem_u32(smc);
    int tid = threadIdx.x, wid = tid >> 5, lane = tid & 31;
    int b  = blockIdx.x / 72;
    int p0 = (blockIdx.x % 72) * 128;

    const float* xt_b = xt + (size_t)b * XTB;
    int c2 = 2 * lane;
    int*    sIdx = (int*)(smc + SM_IDX);
    float2* sFr  = (float2*)(smc + SM_FR);

    int mg = wid & 3;       // m32 group (32 px)
    int nq = wid >> 2;      // n quarter: 2 n8-tiles

    float acc[2][2][4];     // [m16 tile][n8 tile][frag]
#pragma unroll
    for (int m = 0; m < 2; m++)
#pragma unroll
        for (int i = 0; i < 2; i++)
#pragma unroll
            for (int j = 0; j < 4; j++) acc[m][i][j] = 0.f;

    int lr = lane & 7;
    uint32_t la0 = (uint32_t)((mg * 32 + lr + ((lane >> 3) & 1) * 8) * 128 + (lane >> 4) * 16);
    uint32_t lb0 = (uint32_t)((lr + (lane >> 4) * 8) * 128 + ((lane >> 3) & 1) * 16)
                 + (uint32_t)(nq * 2048);

    auto stageB = [&](int k, int buf) {
        const char* src = (const char*)(bst) + (size_t)k * 16384;
        uint32_t dst = sbase + SM_B + (uint32_t)buf * 16384;
#pragma unroll
        for (int i = 0; i < 2; i++) {
            int e = tid + 512 * i;
            CP_ASYNC16(dst + (uint32_t)e * 16, src + (size_t)e * 16);
        }
        CP_COMMIT();
    };
    auto fill = [&](int k, int buf) {
        const int*    si = sIdx + (k << 7);
        const float2* sf = sFr  + (k << 7);
        char* Ab = smc + buf * 32768;
#pragma unroll
        for (int j = 0; j < 8; j++) {
            int px = wid + 16 * j;
            int idx = si[px];
            float2 fr = sf[px];
            const float* base = xt_b + idx + c2;
            float2 g00 = *(const float2*)(base);
            float2 g01 = *(const float2*)(base + CC);
            float2 g10 = *(const float2*)(base + WP * CC);
            float2 g11 = *(const float2*)(base + WP * CC + CC);
            float wy = fr.x, wx = fr.y;
            float w00 = (1.f - wy) * (1.f - wx);
            float w01 = (1.f - wy) * wx;
            float w10 = wy * (1.f - wx);
            float w11 = wy * wx;
            float sx = g00.x*w00 + g01.x*w01 + g10.x*w10 + g11.x*w11;
            float sy = g00.y*w00 + g01.y*w01 + g10.y*w10 + g11.y*w11;
            uint32_t hp, lp;
            BF16_SPLIT(sx, sy, hp, lp);
            uint32_t sw = SW128((uint32_t)(px * 128 + lane * 4));
            *(uint32_t*)(Ab + sw)         = hp;
            *(uint32_t*)(Ab + 16384 + sw) = lp;
        }
    };

    // prologue: idx/frac (1152), stage B0, fill A0
    {
        size_t gb = (size_t)(b * 9) * HW + p0;
        for (int i = tid; i < 1152; i += 512) {
            int t = i >> 7, px = i & 127;
            size_t g = gb + (size_t)t * HW + px;
            sIdx[i] = pidx[g];
            sFr[i]  = pw2[g];
        }
    }
    stageB(0, 0);
    __syncthreads();
    fill(0, 0);
    CP_WAIT0();
    __syncthreads();

    for (int k = 0; k < 9; k++) {
        int buf = k & 1;
        if (k < 8) stageB(k + 1, buf ^ 1);

        uint32_t Abase = sbase + (uint32_t)buf * 32768;
        uint32_t Bbase = sbase + SM_B + (uint32_t)buf * 16384;
#pragma unroll
        for (int ks = 0; ks < 4; ks++) {
            uint32_t lb = SW128(lb0 + ks * 32);
            uint32_t bh[4], bl[4];
            LDSM_X4(bh[0], bh[1], bh[2], bh[3], Bbase + lb);
            LDSM_X4(bl[0], bl[1], bl[2], bl[3], Bbase + 8192 + lb);
#pragma unroll
            for (int mt = 0; mt < 2; mt++) {
                uint32_t la = SW128(la0 + (uint32_t)(mt * 2048) + ks * 32);
                uint32_t ah0, ah1, ah2, ah3, al0, al1, al2, al3;
                LDSM_X4(ah0, ah1, ah2, ah3, Abase + la);
                LDSM_X4(al0, al1, al2, al3, Abase + la + 16384);
                MMA16816(acc[mt][0], ah0, ah1, ah2, ah3, bh[0], bh[1]);
                MMA16816(acc[mt][1], ah0, ah1, ah2, ah3, bh[2], bh[3]);
                MMA16816(acc[mt][0], al0, al1, al2, al3, bh[0], bh[1]);
                MMA16816(acc[mt][1], al0, al1, al2, al3, bh[2], bh[3]);
                MMA16816(acc[mt][0], ah0, ah1, ah2, ah3, bl[0], bl[1]);
                MMA16816(acc[mt][1], ah0, ah1, ah2, ah3, bl[2], bl[3]);
            }
        }

        if (k < 8) {
            fill(k + 1, buf ^ 1);
            CP_WAIT0();
        }
        __syncthreads();
    }

    // epilogue
    int ob0 = 2 * (lane & 3);
    float* outb = out + (size_t)b * OO * HW;
#pragma unroll
    for (int mt = 0; mt < 2; mt++) {
        int px0 = p0 + mg * 32 + mt * 16 + (lane >> 2);
#pragma unroll
        for (int nt = 0; nt < 2; nt++) {
            int o = (nq * 2 + nt) * 8 + ob0;
            float b0 = cb[o], b1 = cb[o + 1];
            outb[(size_t)o * HW + px0]           = acc[mt][nt][0] + b0;
            outb[(size_t)(o + 1) * HW + px0]     = acc[mt][nt][1] + b1;
            outb[(size_t)o * HW + px0 + 8]       = acc[mt][nt][2] + b0;
            outb[(size_t)(o + 1) * HW + px0 + 8] = acc[mt][nt][3] + b1;
        }
    }
}

// ---------------- launch ---------------------------------------------------------
extern "C" void kernel_launch(void* const* d_in, const int* in_sizes, int n_in,
                              void* d_out, int out_size) {
    const float* x  = (const float*)d_in[0];
    const float* ow = (const float*)d_in[1];
    const float* ob = (const float*)d_in[2];
    const float* cw = (const float*)d_in[3];
    const float* cb = (const float*)d_in[4];
    float* out = (float*)d_out;

    float* xt;
    int* pidx;
    float2* pw2;
    ushort_t *bst, *obst;
    cudaGetSymbolAddress((void**)&xt,   g_xt);
    cudaGetSymbolAddress((void**)&pidx, g_pidx);
    cudaGetSymbolAddress((void**)&pw2,  g_pw2);
    cudaGetSymbolAddress((void**)&bst,  g_bst);
    cudaGetSymbolAddress((void**)&obst, g_obst);

    cudaFuncSetAttribute(offset_mma_kernel,
                         cudaFuncAttributeMaxDynamicSharedMemorySize, OSM_TOT);
    cudaFuncSetAttribute(fused_mma_kernel,
                         cudaFuncAttributeMaxDynamicSharedMemorySize, SM_TOT);

    transpose_x_kernel<<<4608, 256>>>(x, xt);
    build_weights_kernel<<<144, 256>>>(cw, ow, bst, obst);
    offset_mma_kernel<<<1152, 256, OSM_TOT>>>(xt, obst, ob, pidx, pw2);
    fused_mma_kernel<<<576, 512, SM_TOT>>>(xt, pidx, pw2, bst, cb, out);
}

// round 17
// speedup vs baseline: 1.0376x; 1.0376x over previous
#include <cuda_runtime.h>
#include <cuda_bf16.h>
#include <cstdint>

#define BB 8
#define CC 64
#define OO 64
#define HH 96
#define WW 96
#define HW (HH*WW)
#define K2 9
#define NOFF 18
#define WP 100              // padded width/height
#define XTB (WP*WP*CC)

typedef unsigned long long ull;
typedef unsigned short ushort_t;

#define SW128(off) ((off) ^ (((off) >> 3) & 0x70))

__device__ __forceinline__ uint32_t smem_u32(const void* p) {
    uint32_t a;
    asm("{ .reg .u64 t; cvta.to.shared.u64 t, %1; cvt.u32.u64 %0, t; }" : "=r"(a) : "l"(p));
    return a;
}

#define LDSM_X4(r0, r1, r2, r3, addr) \
    asm volatile("ldmatrix.sync.aligned.m8n8.x4.shared.b16 {%0,%1,%2,%3}, [%4];" \
                 : "=r"(r0), "=r"(r1), "=r"(r2), "=r"(r3) : "r"(addr))

#define MMA16816(ac, a0, a1, a2, a3, b0, b1) \
    asm volatile("mma.sync.aligned.m16n8k16.row.col.f32.bf16.bf16.f32 " \
                 "{%0,%1,%2,%3}, {%4,%5,%6,%7}, {%8,%9}, {%0,%1,%2,%3};" \
                 : "+f"((ac)[0]), "+f"((ac)[1]), "+f"((ac)[2]), "+f"((ac)[3]) \
                 : "r"(a0), "r"(a1), "r"(a2), "r"(a3), "r"(b0), "r"(b1))

#define CP_ASYNC16(dst, src) \
    asm volatile("cp.async.cg.shared.global [%0], [%1], 16;" :: "r"(dst), "l"(src))
#define CP_COMMIT() asm volatile("cp.async.commit_group;")
#define CP_WAIT0()  asm volatile("cp.async.wait_group 0;")

#define BF16_SPLIT(sx, sy, hp, lp) do { \
    asm("cvt.rn.bf16x2.f32 %0, %1, %2;" : "=r"(hp) : "f"(sy), "f"(sx)); \
    float _hx = __uint_as_float((hp) << 16); \
    float _hy = __uint_as_float((hp) & 0xffff0000u); \
    asm("cvt.rn.bf16x2.f32 %0, %1, %2;" : "=r"(lp) : "f"((sy) - _hy), "f"((sx) - _hx)); \
} while (0)

// ---------------- scratch -----------------------------------------------------
__device__ float    g_xt[BB * XTB];            // padded NHWC x fp32 (zero border)
__device__ ushort_t g_xth[BB * XTB];           // padded NHWC x bf16 hi
__device__ ushort_t g_xtl[BB * XTB];           // padded NHWC x bf16 lo
__device__ int      g_pidx[BB * K2 * HW];      // base idx (0 => zero corner if far)
__device__ float2   g_pw2[BB * K2 * HW];       // raw fractions (wy, wx)
__device__ ushort_t g_bst[K2 * 2 * 4096];      // conv_w bf16 [tap][hi/lo], SW128
__device__ ushort_t g_obst[K2 * 2 * 2048];     // offset_w bf16 [tap][hi/lo][32n][64c], SW128

// ---------------- transpose NCHW -> padded NHWC (fp32 + bf16 split) ------------
__global__ void transpose_x_kernel(const float* __restrict__ x, float* __restrict__ xt,
                                   ushort_t* __restrict__ xth, ushort_t* __restrict__ xtl) {
    __shared__ float tile[32][33];
    int blk = blockIdx.x;
    int pt = blk % 288, ct = (blk / 288) & 1, b = blk / 576;
    int lx = threadIdx.x & 31, ly = threadIdx.x >> 5;
    int p0 = pt * 32, c0 = ct * 32;
    int h = p0 / WW, w0 = p0 - h * WW;
    const float* xb = x + (size_t)(b * CC + c0) * HW + p0;
#pragma unroll
    for (int i = 0; i < 4; i++) {
        int cc = ly + 8 * i;
        tile[cc][lx] = xb[(size_t)cc * HW + lx];
    }
    __syncthreads();
    size_t obase = (size_t)b * XTB + ((size_t)(h + 2) * WP + (w0 + 2)) * CC + c0;
    float*    xo  = xt  + obase;
    ushort_t* xoh = xth + obase;
    ushort_t* xol = xtl + obase;
#pragma unroll
    for (int i = 0; i < 4; i++) {
        int pp = ly + 8 * i;
        float v = tile[lx][pp];
        __nv_bfloat16 hb = __float2bfloat16(v);
        __nv_bfloat16 lb = __float2bfloat16(v - __bfloat162float(hb));
        xo[(size_t)pp * CC + lx]  = v;
        xoh[(size_t)pp * CC + lx] = *(ushort_t*)&hb;
        xol[(size_t)pp * CC + lx] = *(ushort_t*)&lb;
    }
}

// ---------------- weight prep (both B matrices pre-swizzled) --------------------
__global__ void build_weights_kernel(const float* __restrict__ cw,
                                     const float* __restrict__ ow,
                                     ushort_t* __restrict__ bst,
                                     ushort_t* __restrict__ obst) {
    int idx = blockIdx.x * 256 + threadIdx.x;
    if (idx < K2 * OO * CC) {        // conv_w -> [tap][hi/lo][64o][64c]
        int k = idx / (OO * CC);
        int r = idx % (OO * CC);
        int o = r / CC;
        int c = r % CC;
        float v = cw[(size_t)(o * CC + c) * K2 + k];
        __nv_bfloat16 h = __float2bfloat16(v);
        __nv_bfloat16 l = __float2bfloat16(v - __bfloat162float(h));
        uint32_t sw = SW128((uint32_t)(o * 128 + c * 2)) >> 1;
        bst[(k * 2 + 0) * 4096 + sw] = *(ushort_t*)&h;
        bst[(k * 2 + 1) * 4096 + sw] = *(ushort_t*)&l;
    }
    if (idx < K2 * 32 * CC) {        // offset_w -> [tap][hi/lo][32n pad][64c]
        int k = idx / (32 * CC);
        int r = idx % (32 * CC);
        int n = r / CC;
        int c = r % CC;
        float v = (n < NOFF) ? ow[(size_t)(n * CC + c) * K2 + k] : 0.f;
        __nv_bfloat16 h = __float2bfloat16(v);
        __nv_bfloat16 l = __float2bfloat16(v - __bfloat162float(h));
        uint32_t sw = SW128((uint32_t)(n * 128 + c * 2)) >> 1;
        obst[(k * 2 + 0) * 2048 + sw] = *(ushort_t*)&h;
        obst[(k * 2 + 1) * 2048 + sw] = *(ushort_t*)&l;
    }
}

// ---------------- offset conv as HMMA (3-pass), cp.async A from bf16 xt ---------
// 256 thr, tile 64 px x 32 out, 4 CTAs/SM.
// smem: A 2buf x (hi 8192 + lo 8192) = 32768; B at 32768: 2buf x (hi 4096 + lo 4096)
#define OSM_B   32768
#define OSM_TOT 49152

__global__ void __launch_bounds__(256, 4)
offset_mma_kernel(const ushort_t* __restrict__ xth, const ushort_t* __restrict__ xtl,
                  const ushort_t* __restrict__ obst, const float* __restrict__ ob,
                  int* __restrict__ pidx, float2* __restrict__ pw2)
{
    extern __shared__ char smc[];
    uint32_t sbase = smem_u32(smc);
    int tid = threadIdx.x, wid = tid >> 5, lane = tid & 31;
    int b  = blockIdx.x / 144;
    int p0 = (blockIdx.x % 144) * 64;

    const ushort_t* xth_b = xth + (size_t)b * XTB;
    const ushort_t* xtl_b = xtl + (size_t)b * XTB;
    int mt = wid & 3;      // m16 tile
    int ng = wid >> 2;     // n group: 2 n8-tiles

    float acc[2][4];
#pragma unroll
    for (int i = 0; i < 2; i++)
#pragma unroll
        for (int j = 0; j < 4; j++) acc[i][j] = 0.f;

    int lr = lane & 7;
    uint32_t la0 = (uint32_t)((mt * 16 + lr + ((lane >> 3) & 1) * 8) * 128 + (lane >> 4) * 16);
    uint32_t lb0 = (uint32_t)((ng * 16 + lr + (lane >> 4) * 8) * 128 + ((lane >> 3) & 1) * 16);

    auto stageB = [&](int k, int buf) {
        const char* src = (const char*)(obst) + (size_t)k * 8192;
        uint32_t dst = sbase + OSM_B + (uint32_t)buf * 8192;
        CP_ASYNC16(dst + (uint32_t)tid * 16,         src + (size_t)tid * 16);
        CP_ASYNC16(dst + (uint32_t)(tid + 256) * 16, src + (size_t)(tid + 256) * 16);
    };
    // A fill: pure async copy of swizzled 16B chunks from pre-split bf16 xt
    auto fillA = [&](int k, int buf) {
        int dyk = k / 3, dxk = k % 3;
        uint32_t Ab = sbase + (uint32_t)buf * 16384;
#pragma unroll
        for (int it = 0; it < 2; it++) {
            int e = tid + 256 * it;       // 0..511: px = e>>3, chunk j = e&7
            int px = e >> 3, j = e & 7;
            int p = p0 + px;
            int h = p / WW, w = p - h * WW;
            size_t pix = (size_t)(h + dyk + 1) * WP + (w + dxk + 1);
            uint32_t doff = (uint32_t)(px * 128 + ((j ^ (px & 7)) << 4));
            CP_ASYNC16(Ab + doff,        (const char*)(xth_b + pix * CC) + j * 16);
            CP_ASYNC16(Ab + 8192 + doff, (const char*)(xtl_b + pix * CC) + j * 16);
        }
        CP_COMMIT();
    };

    stageB(0, 0);
    fillA(0, 0);
    CP_WAIT0();
    __syncthreads();

    for (int k = 0; k < 9; k++) {
        int buf = k & 1;
        if (k < 8) {                 // issue next tap's copies before MMA
            stageB(k + 1, buf ^ 1);
            fillA(k + 1, buf ^ 1);
        }

        uint32_t Abase = sbase + (uint32_t)buf * 16384;
        uint32_t Bbase = sbase + OSM_B + (uint32_t)buf * 8192;
#pragma unroll
        for (int ks = 0; ks < 4; ks++) {
            uint32_t la = SW128(la0 + ks * 32);
            uint32_t lb = SW128(lb0 + ks * 32);
            uint32_t ah0, ah1, ah2, ah3, al0, al1, al2, al3;
            LDSM_X4(ah0, ah1, ah2, ah3, Abase + la);
            LDSM_X4(al0, al1, al2, al3, Abase + la + 8192);
            uint32_t bh[4];
            LDSM_X4(bh[0], bh[1], bh[2], bh[3], Bbase + lb);
            MMA16816(acc[0], ah0, ah1, ah2, ah3, bh[0], bh[1]);
            MMA16816(acc[1], ah0, ah1, ah2, ah3, bh[2], bh[3]);
            MMA16816(acc[0], al0, al1, al2, al3, bh[0], bh[1]);
            MMA16816(acc[1], al0, al1, al2, al3, bh[2], bh[3]);
            uint32_t bl[4];
            LDSM_X4(bl[0], bl[1], bl[2], bl[3], Bbase + 4096 + lb);
            MMA16816(acc[0], ah0, ah1, ah2, ah3, bl[0], bl[1]);
            MMA16816(acc[1], ah0, ah1, ah2, ah3, bl[2], bl[3]);
        }

        if (k < 8) CP_WAIT0();
        __syncthreads();
    }

    // ---- epilogue: offsets -> positions, written straight to pidx/pw2 ----
    int px0 = p0 + mt * 16 + (lane >> 2);
#pragma unroll
    for (int nt = 0; nt < 2; nt++) {
        int n0 = ng * 16 + nt * 8 + 2 * (lane & 3);
        int t = n0 >> 1;
        if (t < 9) {
            float bdy = ob[n0], bdx = ob[n0 + 1];
            int tdy = t / 3 - 1, tdx = t % 3 - 1;
#pragma unroll
            for (int half = 0; half < 2; half++) {
                int p = px0 + 8 * half;
                float dy = acc[nt][2 * half]     + bdy;
                float dx = acc[nt][2 * half + 1] + bdx;
                int h = p / WW, w = p - h * WW;
                float py = (float)(h + tdy) + dy;
                float qx = (float)(w + tdx) + dx;
                float fy = floorf(py), fx = floorf(qx);
                int y0 = (int)fy, x0i = (int)fx;
                float wy = py - fy, wx = qx - fx;
                bool far = (y0 < -2) | (y0 > 96) | (x0i < -2) | (x0i > 96);
                int idx = far ? 0 : ((y0 + 2) * WP + (x0i + 2)) * CC;
                size_t gp = ((size_t)(b * 9 + t)) * HW + p;
                pidx[gp] = idx;
                pw2[gp]  = make_float2(wy, wx);
            }
        }
    }
}

// ---------------- fused: 128-px tile, m32n16 warp tile, 512 thr, 2 CTAs/SM ------
// smem: A 2buf x (hi 16384 + lo 16384) = 65536
//       B at 65536: 2buf x (hi 8192 + lo 8192) = 32768
//       sIdx at 98304 (1152 int), sFrac at 102912 (1152 float2)
#define SM_B    65536
#define SM_IDX  98304
#define SM_FR   102912
#define SM_TOT  112128

__global__ void __launch_bounds__(512, 2)
fused_mma_kernel(const float* __restrict__ xt, const int* __restrict__ pidx,
                 const float2* __restrict__ pw2, const ushort_t* __restrict__ bst,
                 const float* __restrict__ cb, float* __restrict__ out)
{
    extern __shared__ char smc[];
    uint32_t sbase = smem_u32(smc);
    int tid = threadIdx.x, wid = tid >> 5, lane = tid & 31;
    int b  = blockIdx.x / 72;
    int p0 = (blockIdx.x % 72) * 128;

    const float* xt_b = xt + (size_t)b * XTB;
    int c2 = 2 * lane;
    int*    sIdx = (int*)(smc + SM_IDX);
    float2* sFr  = (float2*)(smc + SM_FR);

    int mg = wid & 3;       // m32 group (32 px)
    int nq = wid >> 2;      // n quarter: 2 n8-tiles

    float acc[2][2][4];     // [m16 tile][n8 tile][frag]
#pragma unroll
    for (int m = 0; m < 2; m++)
#pragma unroll
        for (int i = 0; i < 2; i++)
#pragma unroll
            for (int j = 0; j < 4; j++) acc[m][i][j] = 0.f;

    int lr = lane & 7;
    uint32_t la0 = (uint32_t)((mg * 32 + lr + ((lane >> 3) & 1) * 8) * 128 + (lane >> 4) * 16);
    uint32_t lb0 = (uint32_t)((lr + (lane >> 4) * 8) * 128 + ((lane >> 3) & 1) * 16)
                 + (uint32_t)(nq * 2048);

    auto stageB = [&](int k, int buf) {
        const char* src = (const char*)(bst) + (size_t)k * 16384;
        uint32_t dst = sbase + SM_B + (uint32_t)buf * 16384;
#pragma unroll
        for (int i = 0; i < 2; i++) {
            int e = tid + 512 * i;
            CP_ASYNC16(dst + (uint32_t)e * 16, src + (size_t)e * 16);
        }
        CP_COMMIT();
    };
    auto fill = [&](int k, int buf) {
        const int*    si = sIdx + (k << 7);
        const float2* sf = sFr  + (k << 7);
        char* Ab = smc + buf * 32768;
#pragma unroll
        for (int j = 0; j < 8; j++) {
            int px = wid + 16 * j;
            int idx = si[px];
            float2 fr = sf[px];
            const float* base = xt_b + idx + c2;
            float2 g00 = *(const float2*)(base);
            float2 g01 = *(const float2*)(base + CC);
            float2 g10 = *(const float2*)(base + WP * CC);
            float2 g11 = *(const float2*)(base + WP * CC + CC);
            float wy = fr.x, wx = fr.y;
            float w00 = (1.f - wy) * (1.f - wx);
            float w01 = (1.f - wy) * wx;
            float w10 = wy * (1.f - wx);
            float w11 = wy * wx;
            float sx = g00.x*w00 + g01.x*w01 + g10.x*w10 + g11.x*w11;
            float sy = g00.y*w00 + g01.y*w01 + g10.y*w10 + g11.y*w11;
            uint32_t hp, lp;
            BF16_SPLIT(sx, sy, hp, lp);
            uint32_t sw = SW128((uint32_t)(px * 128 + lane * 4));
            *(uint32_t*)(Ab + sw)         = hp;
            *(uint32_t*)(Ab + 16384 + sw) = lp;
        }
    };

    // prologue: idx/frac (1152), stage B0, fill A0
    {
        size_t gb = (size_t)(b * 9) * HW + p0;
        for (int i = tid; i < 1152; i += 512) {
            int t = i >> 7, px = i & 127;
            size_t g = gb + (size_t)t * HW + px;
            sIdx[i] = pidx[g];
            sFr[i]  = pw2[g];
        }
    }
    stageB(0, 0);
    __syncthreads();
    fill(0, 0);
    CP_WAIT0();
    __syncthreads();

    for (int k = 0; k < 9; k++) {
        int buf = k & 1;
        if (k < 8) stageB(k + 1, buf ^ 1);

        uint32_t Abase = sbase + (uint32_t)buf * 32768;
        uint32_t Bbase = sbase + SM_B + (uint32_t)buf * 16384;
#pragma unroll
        for (int ks = 0; ks < 4; ks++) {
            uint32_t lb = SW128(lb0 + ks * 32);
            uint32_t bh[4], bl[4];
            LDSM_X4(bh[0], bh[1], bh[2], bh[3], Bbase + lb);
            LDSM_X4(bl[0], bl[1], bl[2], bl[3], Bbase + 8192 + lb);
#pragma unroll
            for (int mt = 0; mt < 2; mt++) {
                uint32_t la = SW128(la0 + (uint32_t)(mt * 2048) + ks * 32);
                uint32_t ah0, ah1, ah2, ah3, al0, al1, al2, al3;
                LDSM_X4(ah0, ah1, ah2, ah3, Abase + la);
                LDSM_X4(al0, al1, al2, al3, Abase + la + 16384);
                MMA16816(acc[mt][0], ah0, ah1, ah2, ah3, bh[0], bh[1]);
                MMA16816(acc[mt][1], ah0, ah1, ah2, ah3, bh[2], bh[3]);
                MMA16816(acc[mt][0], al0, al1, al2, al3, bh[0], bh[1]);
                MMA16816(acc[mt][1], al0, al1, al2, al3, bh[2], bh[3]);
                MMA16816(acc[mt][0], ah0, ah1, ah2, ah3, bl[0], bl[1]);
                MMA16816(acc[mt][1], ah0, ah1, ah2, ah3, bl[2], bl[3]);
            }
        }

        if (k < 8) {
            fill(k + 1, buf ^ 1);
            CP_WAIT0();
        }
        __syncthreads();
    }

    // epilogue
    int ob0 = 2 * (lane & 3);
    float* outb = out + (size_t)b * OO * HW;
#pragma unroll
    for (int mt = 0; mt < 2; mt++) {
        int px0 = p0 + mg * 32 + mt * 16 + (lane >> 2);
#pragma unroll
        for (int nt = 0; nt < 2; nt++) {
            int o = (nq * 2 + nt) * 8 + ob0;
            float b0 = cb[o], b1 = cb[o + 1];
            outb[(size_t)o * HW + px0]           = acc[mt][nt][0] + b0;
            outb[(size_t)(o + 1) * HW + px0]     = acc[mt][nt][1] + b1;
            outb[(size_t)o * HW + px0 + 8]       = acc[mt][nt][2] + b0;
            outb[(size_t)(o + 1) * HW + px0 + 8] = acc[mt][nt][3] + b1;
        }
    }
}

// ---------------- launch ---------------------------------------------------------
extern "C" void kernel_launch(void* const* d_in, const int* in_sizes, int n_in,
                              void* d_out, int out_size) {
    const float* x  = (const float*)d_in[0];
    const float* ow = (const float*)d_in[1];
    const float* ob = (const float*)d_in[2];
    const float* cw = (const float*)d_in[3];
    const float* cb = (const float*)d_in[4];
    float* out = (float*)d_out;

    float* xt;
    ushort_t *xth, *xtl;
    int* pidx;
    float2* pw2;
    ushort_t *bst, *obst;
    cudaGetSymbolAddress((void**)&xt,   g_xt);
    cudaGetSymbolAddress((void**)&xth,  g_xth);
    cudaGetSymbolAddress((void**)&xtl,  g_xtl);
    cudaGetSymbolAddress((void**)&pidx, g_pidx);
    cudaGetSymbolAddress((void**)&pw2,  g_pw2);
    cudaGetSymbolAddress((void**)&bst,  g_bst);
    cudaGetSymbolAddress((void**)&obst, g_obst);

    cudaFuncSetAttribute(offset_mma_kernel,
                         cudaFuncAttributeMaxDynamicSharedMemorySize, OSM_TOT);
    cudaFuncSetAttribute(fused_mma_kernel,
                         cudaFuncAttributeMaxDynamicSharedMemorySize, SM_TOT);

    transpose_x_kernel<<<4608, 256>>>(x, xt, xth, xtl);
    build_weights_kernel<<<144, 256>>>(cw, ow, bst, obst);
    offset_mma_kernel<<<1152, 256, OSM_TOT>>>(xth, xtl, obst, ob, pidx, pw2);
    fused_mma_kernel<<<576, 512, SM_TOT>>>(xt, pidx, pw2, bst, cb, out);
}